// round 16
// baseline (speedup 1.0000x reference)
#include <cuda_runtime.h>
#include <cuda_bf16.h>
#include <math.h>
#include <stdint.h>

#define GMM_D 64
#define GMM_K 64
#define TPB   128
#define WCH   16          // samples per warp-chunk
#define NJ2   16          // ulonglong2 steps (64 floats = 32 pairs = 16 ull2)
#define RXC   17          // chunk row stride (ull2): 272B
#define RW    65          // W tile row stride (ull2): 1040B
#define SCR_STRIDE 17     // transpose scratch row stride (floats, 68B — scalar access only)

typedef unsigned long long ull;

// smem offsets (bytes)
#define XBUF_BYTES 4352                   // 16 * 17 * 16
#define OFF_XB   0                        // 4 warps x 2 bufs x 4352 = 34816
#define OFF_WB   34816                    // 16640
#define OFF_WA   51456                    // 16640
#define OFF_C    68096                    // 256
#define OFF_FLAG 68352
#define SMEM_TOTAL 68368                  // x3 CTAs = 205.1KB <= 228KB

__device__ __forceinline__ ull fma2(ull a, ull b, ull c) {
    ull d; asm("fma.rn.f32x2 %0, %1, %2, %3;" : "=l"(d) : "l"(a), "l"(b), "l"(c)); return d;
}
__device__ __forceinline__ ull mul2(ull a, ull b) {
    ull d; asm("mul.rn.f32x2 %0, %1, %2;" : "=l"(d) : "l"(a), "l"(b)); return d;
}
__device__ __forceinline__ ull pack2(float lo, float hi) {
    ull r; asm("mov.b64 %0, {%1, %2};" : "=l"(r) : "f"(lo), "f"(hi)); return r;
}
__device__ __forceinline__ void unpack2(ull v, float& lo, float& hi) {
    asm("mov.b64 {%0, %1}, %2;" : "=f"(lo), "=f"(hi) : "l"(v));
}
__device__ __forceinline__ uint32_t smem_u32(const void* p) {
    uint32_t a;
    asm("{ .reg .u64 t; cvta.to.shared.u64 t, %1; cvt.u32.u64 %0, t; }" : "=r"(a) : "l"(p));
    return a;
}
__device__ __forceinline__ void cp_async16(uint32_t dst, const void* src) {
    asm volatile("cp.async.cg.shared.global [%0], [%1], 16;" :: "r"(dst), "l"(src));
}
__device__ __forceinline__ void cp_commit() {
    asm volatile("cp.async.commit_group;" ::: "memory");
}
template <int NN>
__device__ __forceinline__ void cp_wait() {
    asm volatile("cp.async.wait_group %0;" :: "n"(NN) : "memory");
}

// stage one 16-sample chunk (jp2-major ull2 layout) into a per-warp buffer
__device__ __forceinline__ void prefetch_chunk(const float* __restrict__ X, int chunk,
                                               uint32_t dstbase, int lane) {
    const char* src = (const char*)(X + (size_t)chunk * WCH * GMM_D);
    #pragma unroll
    for (int i = 0; i < 8; i++) {
        int c   = i * 32 + lane;          // 0..255 16B chunks
        int n   = c >> 4;
        int jp2 = c & 15;
        cp_async16(dstbase + (uint32_t)(jp2 * RXC + n) * 16, src + (size_t)c * 16);
    }
}

// ---------------------------------------------------------------------------
// Warp-autonomous persistent GMM posterior, 3 CTAs/SM (12 warps/SM).
// weighted[n,k] = sum_d x*B[k] (+ x^2*A'[k] if logvars not k-uniform) + C[k];
// k-uniform terms cancel in the log-softmax over k.
// Each WARP independently streams 16-sample chunks (own double-buffered
// cp.async staging; no __syncthreads after init).
// Lane map: sg=lane&1 (sample), kg=lane>>1 (k-group, 0..15).
//   samples: n = chunk*16 + sg + 2m  (m=0..7); k = kg + 16q (q=0..3).
// ---------------------------------------------------------------------------
__global__ void __launch_bounds__(TPB, 3)
gmm_warp(const float* __restrict__ X, const float* __restrict__ mu,
         const float* __restrict__ lv, const float* __restrict__ lp,
         float* __restrict__ out, int N, int nchunks, int nwarps) {
    extern __shared__ char sm[];
    ulonglong2* sWB = (ulonglong2*)(sm + OFF_WB);
    ulonglong2* sWA = (ulonglong2*)(sm + OFF_WA);
    float* sC   = (float*)(sm + OFF_C);
    int*   sFlag= (int*)(sm + OFF_FLAG);

    const int t    = threadIdx.x;
    const int warp = t >> 5;
    const int lane = t & 31;
    const int sg   = lane & 1;
    const int kg   = lane >> 1;

    const uint32_t smb  = smem_u32(sm);
    const uint32_t buf0 = smb + OFF_XB + warp * 2 * XBUF_BYTES;
    const uint32_t buf1 = buf0 + XBUF_BYTES;

    // kick off first chunk prefetch immediately
    const int gwarp = blockIdx.x * 4 + warp;
    if (gwarp < nchunks) prefetch_chunk(X, gwarp, buf0, lane);
    cp_commit();

    if (t == 0) *sFlag = 0;
    __syncthreads();

    // ---- stage W tiles + uniformity flag + C[k] (once per CTA) ----
    {
        const float4* mu4 = (const float4*)mu;
        const float4* lv4 = (const float4*)lv;
        int bad = 0;
        #pragma unroll
        for (int i = 0; i < 8; i++) {
            int idx = i * TPB + t;        // 0..1023
            int jp2 = idx & 15;
            int k   = idx >> 4;
            float4 l  = lv4[k * 16 + jp2];
            float4 m  = mu4[k * 16 + jp2];
            float4 l0 = lv4[jp2];
            bad |= (__float_as_int(l.x) != __float_as_int(l0.x)) |
                   (__float_as_int(l.y) != __float_as_int(l0.y)) |
                   (__float_as_int(l.z) != __float_as_int(l0.z)) |
                   (__float_as_int(l.w) != __float_as_int(l0.w));
            float e0 = __expf(-l.x), e1 = __expf(-l.y);
            float e2 = __expf(-l.z), e3 = __expf(-l.w);
            ulonglong2 B, A;
            B.x = pack2(m.x * e0, m.y * e1);     B.y = pack2(m.z * e2, m.w * e3);
            A.x = pack2(-0.5f * e0, -0.5f * e1); A.y = pack2(-0.5f * e2, -0.5f * e3);
            sWB[jp2 * RW + k] = B;
            sWA[jp2 * RW + k] = A;
        }
        if (bad) atomicOr(sFlag, 1);
        if (t < GMM_K) {
            float s = 0.f;
            #pragma unroll 8
            for (int d = 0; d < GMM_D; d++) {
                float l = lv[t * GMM_D + d];
                float m = mu[t * GMM_D + d];
                s += l + m * m * __expf(-l);
            }
            sC[t] = -0.5f * s + lp[t];
        }
    }
    __syncthreads();                      // LAST block barrier

    const int general = *sFlag;
    float ck[4];
    #pragma unroll
    for (int q = 0; q < 4; q++) ck[q] = sC[kg + 16 * q];

    const ulonglong2* wb = sWB + kg;
    const ulonglong2* wa = sWA + kg;

    int bufi = 0;
    for (int chunk = gwarp; chunk < nchunks; chunk += nwarps) {
        const int nxt = chunk + nwarps;
        const uint32_t cur = bufi ? buf1 : buf0;
        __syncwarp();                     // prev-iter scratch/GEMM use of other buf done
        if (nxt < nchunks) {
            prefetch_chunk(X, nxt, bufi ? buf0 : buf1, lane);
            cp_commit();
            cp_wait<1>();
        } else {
            cp_wait<0>();
        }
        __syncwarp();                     // all lanes' cp.async for cur visible

        const ulonglong2* xb = (const ulonglong2*)(sm + (cur - smb)) + sg;

        ull acc[8][4];
        #pragma unroll
        for (int m = 0; m < 8; m++)
            #pragma unroll
            for (int q = 0; q < 4; q++) acc[m][q] = 0ull;

        if (!general) {
            #pragma unroll
            for (int jp2 = 0; jp2 < NJ2; jp2++) {
                ulonglong2 wv[4], xv[8];
                #pragma unroll
                for (int q = 0; q < 4; q++) wv[q] = wb[jp2 * RW + 16 * q];
                #pragma unroll
                for (int m = 0; m < 8; m++) xv[m] = xb[jp2 * RXC + 2 * m];
                #pragma unroll
                for (int m = 0; m < 8; m++)
                    #pragma unroll
                    for (int q = 0; q < 4; q++) {
                        acc[m][q] = fma2(xv[m].x, wv[q].x, acc[m][q]);
                        acc[m][q] = fma2(xv[m].y, wv[q].y, acc[m][q]);
                    }
            }
        } else {
            #pragma unroll 4
            for (int jp2 = 0; jp2 < NJ2; jp2++) {
                ulonglong2 wv[4], wv2[4], xv[8];
                #pragma unroll
                for (int q = 0; q < 4; q++) { wv[q]  = wb[jp2 * RW + 16 * q];
                                              wv2[q] = wa[jp2 * RW + 16 * q]; }
                #pragma unroll
                for (int m = 0; m < 8; m++) xv[m] = xb[jp2 * RXC + 2 * m];
                #pragma unroll
                for (int m = 0; m < 8; m++) {
                    ull xqx = mul2(xv[m].x, xv[m].x);
                    ull xqy = mul2(xv[m].y, xv[m].y);
                    #pragma unroll
                    for (int q = 0; q < 4; q++) {
                        acc[m][q] = fma2(xv[m].x, wv[q].x, acc[m][q]);
                        acc[m][q] = fma2(xv[m].y, wv[q].y, acc[m][q]);
                        acc[m][q] = fma2(xqx, wv2[q].x, acc[m][q]);
                        acc[m][q] = fma2(xqy, wv2[q].y, acc[m][q]);
                    }
                }
            }
        }

        // ---- finalize + warp-local logsumexp over k ----
        float w[8][4], lse[8];
        #pragma unroll
        for (int q = 0; q < 4; q++)
            #pragma unroll
            for (int m = 0; m < 8; m++) {
                float lo, hi; unpack2(acc[m][q], lo, hi);
                w[m][q] = lo + hi + ck[q];
            }
        #pragma unroll
        for (int m = 0; m < 8; m++) {
            float mx = w[m][0];
            #pragma unroll
            for (int q = 1; q < 4; q++) mx = fmaxf(mx, w[m][q]);
            mx = fmaxf(mx, __shfl_xor_sync(0xffffffffu, mx, 2));
            mx = fmaxf(mx, __shfl_xor_sync(0xffffffffu, mx, 4));
            mx = fmaxf(mx, __shfl_xor_sync(0xffffffffu, mx, 8));
            mx = fmaxf(mx, __shfl_xor_sync(0xffffffffu, mx, 16));
            float s = 0.f;
            #pragma unroll
            for (int q = 0; q < 4; q++) s += __expf(w[m][q] - mx);
            s += __shfl_xor_sync(0xffffffffu, s, 2);
            s += __shfl_xor_sync(0xffffffffu, s, 4);
            s += __shfl_xor_sync(0xffffffffu, s, 8);
            s += __shfl_xor_sync(0xffffffffu, s, 16);
            lse[m] = mx + __logf(s);
        }

        // ---- transpose through the just-consumed X buffer ----
        // scr[k][n]: 64 rows x stride-17 floats (4352B). Scalar STS (conflict-
        // free: 17 odd => 17*kg injective mod 32) and scalar LDS readback
        // (68B row stride is NOT 16B-aligned — no vector smem loads here).
        __syncwarp();                     // all GEMM reads of cur complete
        float* scr = (float*)(sm + (cur - smb));
        #pragma unroll
        for (int q = 0; q < 4; q++) {
            const int k = kg + 16 * q;
            #pragma unroll
            for (int m = 0; m < 8; m++)
                scr[k * SCR_STRIDE + sg + 2 * m] = w[m][q] - lse[m];
        }
        __syncwarp();
        {
            const int n0c = chunk * WCH;
            const int r0  = lane >> 2;    // 0..7
            const int c   = 4 * (lane & 3);
            #pragma unroll
            for (int i = 0; i < 8; i++) {
                const int k = i * 8 + r0;
                const float* p = &scr[k * SCR_STRIDE + c];
                float4 v;
                v.x = p[0]; v.y = p[1]; v.z = p[2]; v.w = p[3];
                *(float4*)(out + (size_t)k * N + n0c + c) = v;
            }
        }
        bufi ^= 1;
    }
}

extern "C" void kernel_launch(void* const* d_in, const int* in_sizes, int n_in,
                              void* d_out, int out_size) {
    const float* X  = (const float*)d_in[0];
    const float* mu = (const float*)d_in[1];
    const float* lv = (const float*)d_in[2];
    const float* lp = (const float*)d_in[3];
    float* out = (float*)d_out;

    const int K = in_sizes[3];            // 64
    const int D = in_sizes[1] / K;        // 64
    const int N = in_sizes[0] / D;        // 131072

    const int nchunks = N / WCH;          // 8192
    int grid = 444;                       // 3 per SM x 148 SMs
    const int nwarps = grid * 4;

    cudaFuncSetAttribute(gmm_warp, cudaFuncAttributeMaxDynamicSharedMemorySize, SMEM_TOTAL);
    gmm_warp<<<grid, TPB, SMEM_TOTAL>>>(X, mu, lv, lp, out, N, nchunks, nwarps);
}